// round 1
// baseline (speedup 1.0000x reference)
#include <cuda_runtime.h>
#include <cstddef>

// Sparsemax via bisection (alpha=2), replicating the reference's fp32 bisection
// semantics but only over the candidate set {x : x > max-1}, since every
// bisection iterate tau_m exceeds tau_lo = max-1 and all other elements
// contribute exactly 0 to f(tau) = sum(max(x-tau,0)) - 1.

#define SPM_D    32000
#define SPM_CAP  4096   // candidate buffer (floats). For N(0,1) rows K ~ 5-30.

__device__ __forceinline__ float warp_max(float v) {
#pragma unroll
    for (int o = 16; o; o >>= 1) v = fmaxf(v, __shfl_xor_sync(0xffffffffu, v, o));
    return v;
}
__device__ __forceinline__ float warp_sum(float v) {
#pragma unroll
    for (int o = 16; o; o >>= 1) v += __shfl_xor_sync(0xffffffffu, v, o);
    return v;
}

template <int NT>
__global__ __launch_bounds__(NT, 3)
void sparsemax_bisect_kernel(const float* __restrict__ X,
                             float* __restrict__ Y, int d) {
    const int row = blockIdx.x;
    const int tid = threadIdx.x;
    const int d4  = d >> 2;

    const float4* __restrict__ x4 =
        reinterpret_cast<const float4*>(X + (size_t)row * (size_t)d);
    float4* __restrict__ y4 =
        reinterpret_cast<float4*>(Y + (size_t)row * (size_t)d);

    __shared__ float s_red[NT / 32];
    __shared__ float s_cand[SPM_CAP];
    __shared__ int   s_cnt;
    __shared__ float s_tau, s_inv, s_f;

    if (tid == 0) s_cnt = 0;

    // ---- Pass 1: row max ----
    float mx = -3.402823466e38f;
#pragma unroll 4
    for (int i = tid; i < d4; i += NT) {
        float4 v = x4[i];
        mx = fmaxf(mx, fmaxf(fmaxf(v.x, v.y), fmaxf(v.z, v.w)));
    }
    mx = warp_max(mx);
    if ((tid & 31) == 0) s_red[tid >> 5] = mx;
    __syncthreads();
    if (tid < 32) {
        float m = (tid < NT / 32) ? s_red[tid] : -3.402823466e38f;
        m = warp_max(m);
        if (tid == 0) s_tau = m;  // temp: broadcast max
    }
    __syncthreads();
    const float mxv     = s_tau;
    const float tau_lo0 = mxv - 1.0f;
    const float inv_d   = 1.0f / (float)d;
    __syncthreads();  // everyone has read mxv before s_tau is reused

    // ---- Pass 2: gather candidates > tau_lo (L2-resident re-read) ----
#pragma unroll 4
    for (int i = tid; i < d4; i += NT) {
        float4 v = x4[i];
        if (v.x > tau_lo0) { int p = atomicAdd(&s_cnt, 1); if (p < SPM_CAP) s_cand[p] = v.x; }
        if (v.y > tau_lo0) { int p = atomicAdd(&s_cnt, 1); if (p < SPM_CAP) s_cand[p] = v.y; }
        if (v.z > tau_lo0) { int p = atomicAdd(&s_cnt, 1); if (p < SPM_CAP) s_cand[p] = v.z; }
        if (v.w > tau_lo0) { int p = atomicAdd(&s_cnt, 1); if (p < SPM_CAP) s_cand[p] = v.w; }
    }
    __syncthreads();
    const int K = s_cnt;

    if (K <= SPM_CAP) {
        // ---- Bisection on warp 0 over the tiny candidate list ----
        if (tid < 32) {
            float tlo    = tau_lo0;
            float tau_hi = mxv - inv_d;
            float dm     = tau_hi - tlo;

            float a = 0.0f;
            for (int i = tid; i < K; i += 32) a += fmaxf(s_cand[i] - tlo, 0.0f);
            const float flo = warp_sum(a) - 1.0f;

            float tm = tlo, fm = flo;
            if (K <= 32) {
                float v = (tid < K) ? s_cand[tid] : -3.402823466e38f;
                for (int it = 0; it < 50; ++it) {
                    dm *= 0.5f;
                    tm = tlo + dm;
                    float s = warp_sum(fmaxf(v - tm, 0.0f));
                    fm = s - 1.0f;
                    if (fm * flo >= 0.0f) tlo = tm;
                }
            } else {
                for (int it = 0; it < 50; ++it) {
                    dm *= 0.5f;
                    tm = tlo + dm;
                    float s = 0.0f;
                    for (int i = tid; i < K; i += 32)
                        s += fmaxf(s_cand[i] - tm, 0.0f);
                    s = warp_sum(s);
                    fm = s - 1.0f;
                    if (fm * flo >= 0.0f) tlo = tm;
                }
            }
            if (tid == 0) { s_tau = tm; s_inv = 1.0f / (fm + 1.0f); }
        }
        __syncthreads();
    } else {
        // ---- Fallback (overflow): block-wide bisection over the full row ----
        float tlo    = tau_lo0;
        float tau_hi = mxv - inv_d;
        float dm     = tau_hi - tlo;

        float a = 0.0f;
        for (int i = tid; i < d4; i += NT) {
            float4 v = x4[i];
            a += fmaxf(v.x - tlo, 0.0f) + fmaxf(v.y - tlo, 0.0f) +
                 fmaxf(v.z - tlo, 0.0f) + fmaxf(v.w - tlo, 0.0f);
        }
        a = warp_sum(a);
        if ((tid & 31) == 0) s_red[tid >> 5] = a;
        __syncthreads();
        if (tid < 32) {
            float t = (tid < NT / 32) ? s_red[tid] : 0.0f;
            t = warp_sum(t);
            if (tid == 0) s_f = t;
        }
        __syncthreads();
        const float flo = s_f - 1.0f;

        float tm = tlo, fm = flo;
        for (int it = 0; it < 50; ++it) {
            dm *= 0.5f;
            tm = tlo + dm;
            float s = 0.0f;
            for (int i = tid; i < d4; i += NT) {
                float4 v = x4[i];
                s += fmaxf(v.x - tm, 0.0f) + fmaxf(v.y - tm, 0.0f) +
                     fmaxf(v.z - tm, 0.0f) + fmaxf(v.w - tm, 0.0f);
            }
            s = warp_sum(s);
            __syncthreads();
            if ((tid & 31) == 0) s_red[tid >> 5] = s;
            __syncthreads();
            if (tid < 32) {
                float t = (tid < NT / 32) ? s_red[tid] : 0.0f;
                t = warp_sum(t);
                if (tid == 0) s_f = t;
            }
            __syncthreads();
            fm = s_f - 1.0f;
            if (fm * flo >= 0.0f) tlo = tm;
        }
        if (tid == 0) { s_tau = tm; s_inv = 1.0f / (fm + 1.0f); }
        __syncthreads();
    }

    const float tau = s_tau;
    const float inv = s_inv;

    // ---- Pass 3: write p = max(x - tau, 0) / sum(p)  (streaming stores) ----
#pragma unroll 4
    for (int i = tid; i < d4; i += NT) {
        float4 v = x4[i];
        float4 r;
        r.x = fmaxf(v.x - tau, 0.0f) * inv;
        r.y = fmaxf(v.y - tau, 0.0f) * inv;
        r.z = fmaxf(v.z - tau, 0.0f) * inv;
        r.w = fmaxf(v.w - tau, 0.0f) * inv;
        __stcs(&y4[i], r);
    }
}

extern "C" void kernel_launch(void* const* d_in, const int* in_sizes, int n_in,
                              void* d_out, int out_size) {
    const float* X = (const float*)d_in[0];
    float* Y       = (float*)d_out;
    const int d    = SPM_D;
    const int rows = in_sizes[0] / d;

    constexpr int NT = 512;
    sparsemax_bisect_kernel<NT><<<rows, NT>>>(X, Y, d);
}